// round 1
// baseline (speedup 1.0000x reference)
#include <cuda_runtime.h>

// FirUpsample2D fused kernel.
// Reference = convT(x, W, up=2, pad=2) -> depthwise FIR blur(4x4, [1,3,3,1]^2/16) -> +bias.
// Composition: out[n,oc,2*oh+ph,2*ow+pw] = bias[oc]
//    + sum_c sum_{th,tw in 3x3} x[n,c,oh-1+th,ow-1+tw] * S[p][oc][c][th][tw]
// where S[p][th][tw] = Keff[2*th + 1-ph][2*tw + 1-pw],
//       Keff[eh][ew]  = sum_{uh,uw} w[uh][uw] * kq[eh-uh]*kq[ew-uw],  kq = {.25,.75,.75,.25}
// i.e. 4 parity-specialized ordinary 3x3 convs on the 64x64 input.

#define NB   8
#define CIN  256
#define OCH  256
#define HIN  64

// Effective weights, layout [p][c][k=th*3+tw][oc]  (oc contiguous for coalesced tile loads)
__device__ float g_Weff[4 * CIN * 9 * OCH];   // 9.44 MB scratch

__global__ void prep_weff_kernel(const float* __restrict__ weight) {
    int idx = blockIdx.x * blockDim.x + threadIdx.x;   // 0 .. 65535  (c, oc)
    int oc = idx & 255;
    int c  = idx >> 8;

    const float kq[4] = {0.25f, 0.75f, 0.75f, 0.25f};

    float w[3][3];
#pragma unroll
    for (int uh = 0; uh < 3; uh++)
#pragma unroll
        for (int uw = 0; uw < 3; uw++)
            w[uh][uw] = weight[((oc * CIN + c) * 3 + uh) * 3 + uw];

    float Keff[6][6];
#pragma unroll
    for (int a = 0; a < 6; a++)
#pragma unroll
        for (int b = 0; b < 6; b++)
            Keff[a][b] = 0.0f;

#pragma unroll
    for (int uh = 0; uh < 3; uh++)
#pragma unroll
        for (int uw = 0; uw < 3; uw++) {
            float wv = w[uh][uw];
#pragma unroll
            for (int vh = 0; vh < 4; vh++)
#pragma unroll
                for (int vw = 0; vw < 4; vw++)
                    Keff[uh + vh][uw + vw] += wv * kq[vh] * kq[vw];
        }

#pragma unroll
    for (int ph = 0; ph < 2; ph++)
#pragma unroll
        for (int pw = 0; pw < 2; pw++) {
            int p = ph * 2 + pw;
#pragma unroll
            for (int th = 0; th < 3; th++)
#pragma unroll
                for (int tw = 0; tw < 3; tw++) {
                    int eh = 2 * th + 1 - ph;
                    int ew = 2 * tw + 1 - pw;
                    g_Weff[(((size_t)p * CIN + c) * 9 + th * 3 + tw) * OCH + oc] =
                        Keff[eh][ew];
                }
        }
}

// Main conv: grid = (32 spatial tiles, 2 oc-tiles, N*4 parities), 256 threads.
// Block tile: 128 oc x (8 rows x 16 cols) positions; thread tile 8 oc x 8 pos.
__global__ __launch_bounds__(256) void conv_main_kernel(
    const float* __restrict__ x,
    const float* __restrict__ bias,
    float* __restrict__ out)
{
    __shared__ float Ws[72 * 128];        // [c*9+k][oc_local]   36.9 KB
    __shared__ float Xs[8][10][20];       // [c][row][col]        6.4 KB

    const int tid = threadIdx.x;
    const int bx  = blockIdx.x;           // 0..31 spatial tile
    const int ocb = blockIdx.y;           // 0..1
    const int nz  = blockIdx.z;           // n*4 + p
    const int n   = nz >> 2;
    const int p   = nz & 3;
    const int ph  = p >> 1, pw = p & 1;

    const int ty  = bx >> 2, tx = bx & 3;
    const int ih0 = ty * 8;               // base oh of tile
    const int iw0 = tx * 16;              // base ow of tile
    const int oc_base = ocb * 128;

    const int m_t = tid & 15;             // oc group: 8 oc each
    const int n_t = tid >> 4;             // position group: 8 pos each
    const int row_local = n_t & 7;
    const int x0 = (n_t >> 3) * 8;

    float acc[8][8];
#pragma unroll
    for (int i = 0; i < 8; i++)
#pragma unroll
        for (int j = 0; j < 8; j++)
            acc[i][j] = 0.0f;

    const float* wbase = g_Weff + (size_t)p * (CIN * 9 * OCH);

    for (int c0 = 0; c0 < CIN; c0 += 8) {
        // ---- load weight tile: 72 rows x 128 oc  (2304 float4, 9 per thread)
#pragma unroll
        for (int it = 0; it < 9; it++) {
            int v    = it * 256 + tid;        // 0..2303
            int row  = v >> 5;                // 0..71
            int lane = v & 31;
            int cc   = row / 9;
            int kk   = row - cc * 9;
            const float4* src = reinterpret_cast<const float4*>(
                wbase + ((size_t)(c0 + cc) * 9 + kk) * OCH + oc_base);
            reinterpret_cast<float4*>(Ws)[v] = src[lane];
        }
        // ---- load input tile with halo: 8 ch x 10 rows x 18 cols (zero padded)
        for (int e = tid; e < 8 * 10 * 18; e += 256) {
            int cc  = e / 180;
            int rem = e - cc * 180;
            int r   = rem / 18;
            int col = rem - r * 18;
            int gh  = ih0 - 1 + r;
            int gw  = iw0 - 1 + col;
            float v = 0.0f;
            if ((unsigned)gh < 64u && (unsigned)gw < 64u)
                v = x[(((size_t)n * CIN + (c0 + cc)) * 64 + gh) * 64 + gw];
            Xs[cc][r][col] = v;
        }
        __syncthreads();

#pragma unroll 1
        for (int c = 0; c < 8; c++) {
#pragma unroll
            for (int kh = 0; kh < 3; kh++) {
                float xr[10];
#pragma unroll
                for (int j = 0; j < 10; j++)
                    xr[j] = Xs[c][row_local + kh][x0 + j];
#pragma unroll
                for (int kw = 0; kw < 3; kw++) {
                    const float4* wp = reinterpret_cast<const float4*>(
                        &Ws[(c * 9 + kh * 3 + kw) * 128 + m_t * 8]);
                    float4 wa = wp[0];
                    float4 wb = wp[1];
                    float wr[8] = {wa.x, wa.y, wa.z, wa.w,
                                   wb.x, wb.y, wb.z, wb.w};
#pragma unroll
                    for (int i = 0; i < 8; i++)
#pragma unroll
                        for (int j = 0; j < 8; j++)
                            acc[i][j] = fmaf(wr[i], xr[j + kw], acc[i][j]);
                }
            }
        }
        __syncthreads();
    }

    // ---- epilogue: interleaved quadrant write + bias
    const int oh = ih0 + row_local;
#pragma unroll
    for (int i = 0; i < 8; i++) {
        int oc = oc_base + m_t * 8 + i;
        float bv = bias[oc];
        size_t base = (((size_t)n * OCH + oc) * 128 + (2 * oh + ph)) * 128 + pw;
#pragma unroll
        for (int j = 0; j < 8; j++) {
            int ow = iw0 + x0 + j;
            out[base + 2 * ow] = acc[i][j] + bv;
        }
    }
}

extern "C" void kernel_launch(void* const* d_in, const int* in_sizes, int n_in,
                              void* d_out, int out_size) {
    const float* hidden = (const float*)d_in[0];   // (8,256,64,64)
    const float* weight = (const float*)d_in[1];   // (256,256,3,3)
    const float* bias   = (const float*)d_in[2];   // (256,)
    float* out = (float*)d_out;                    // (8,256,128,128)

    prep_weff_kernel<<<256, 256>>>(weight);
    conv_main_kernel<<<dim3(32, 2, 32), 256>>>(hidden, bias, out);
}

// round 3
// speedup vs baseline: 2.2907x; 2.2907x over previous
#include <cuda_runtime.h>
#include <cuda_bf16.h>
#include <cstdint>

// ============================================================================
// FirUpsample2D as implicit GEMM on mma.sync (bf16 3-term split, fp32 accum).
// out[n,oc,2*oh+ph,2*ow+pw] = bias[oc] + sum_{c,th,tw} x[n,c,oh-1+th,ow-1+tw]
//                                        * S[p][oc][c][th][tw]
// Per parity p: C[128 oc x 128 pos] += A[128 x 64] * B[64 x 128] over 36 chunks.
// ============================================================================

#define CIN 256
#define OCH 256

// split weights, row-major [p*2+half][kc=36][m=128][k=64] bf16
__device__ __align__(16) unsigned char g_Wh[8 * 36 * 16384];
__device__ __align__(16) unsigned char g_Wl[8 * 36 * 16384];
// split input, packed c-pairs: word[(n*128+c2)*4096 + h*64 + w] = (bf16(c=2*c2), bf16(c=2*c2+1))
__device__ __align__(16) uint32_t g_Xh[8 * 128 * 4096];
__device__ __align__(16) uint32_t g_Xl[8 * 128 * 4096];

__device__ __forceinline__ uint32_t swz(uint32_t o) { return o ^ ((o >> 3) & 0x70); }

__device__ __forceinline__ uint32_t smem_u32(const void* p) {
    uint32_t a;
    asm("{ .reg .u64 t; cvta.to.shared.u64 t, %1; cvt.u32.u64 %0, t; }" : "=r"(a) : "l"(p));
    return a;
}

#define CP16(d, s) asm volatile("cp.async.cg.shared.global [%0], [%1], 16;" :: "r"(d), "l"(s) : "memory")
#define CP4Z(d, s, z) asm volatile("cp.async.ca.shared.global [%0], [%1], 4, %2;" :: "r"(d), "l"(s), "r"(z) : "memory")
#define CP_COMMIT() asm volatile("cp.async.commit_group;" ::: "memory")
#define CP_WAIT1() asm volatile("cp.async.wait_group 1;" ::: "memory")
#define CP_WAIT0() asm volatile("cp.async.wait_group 0;" ::: "memory")

#define LDSM4(r, a) asm volatile( \
    "ldmatrix.sync.aligned.m8n8.x4.shared.b16 {%0,%1,%2,%3}, [%4];" \
    : "=r"((r)[0]), "=r"((r)[1]), "=r"((r)[2]), "=r"((r)[3]) : "r"(a))
#define LDSM2(r, a) asm volatile( \
    "ldmatrix.sync.aligned.m8n8.x2.shared.b16 {%0,%1}, [%2];" \
    : "=r"((r)[0]), "=r"((r)[1]) : "r"(a))

#define MMA(c, a, b) asm volatile( \
    "mma.sync.aligned.m16n8k16.row.col.f32.bf16.bf16.f32 " \
    "{%0,%1,%2,%3},{%4,%5,%6,%7},{%8,%9},{%0,%1,%2,%3};" \
    : "+f"((c)[0]), "+f"((c)[1]), "+f"((c)[2]), "+f"((c)[3]) \
    : "r"((a)[0]), "r"((a)[1]), "r"((a)[2]), "r"((a)[3]), "r"((b)[0]), "r"((b)[1]))

// ---------------------------------------------------------------------------
// prep 1: Weff = conv-weight composed with FIR quarter-kernel, split h/l bf16
// grid <<<256,256>>>: blockIdx.x = oc, tid = c
// ---------------------------------------------------------------------------
__global__ void prep_weff_kernel(const float* __restrict__ weight) {
    int oc = blockIdx.x;
    int c  = threadIdx.x;
    const float kq[4] = {0.25f, 0.75f, 0.75f, 0.25f};

    float w[3][3];
#pragma unroll
    for (int uh = 0; uh < 3; uh++)
#pragma unroll
        for (int uw = 0; uw < 3; uw++)
            w[uh][uw] = weight[((oc * CIN + c) * 3 + uh) * 3 + uw];

    float Keff[6][6];
#pragma unroll
    for (int a = 0; a < 6; a++)
#pragma unroll
        for (int b = 0; b < 6; b++) Keff[a][b] = 0.0f;
#pragma unroll
    for (int uh = 0; uh < 3; uh++)
#pragma unroll
        for (int uw = 0; uw < 3; uw++) {
            float wv = w[uh][uw];
#pragma unroll
            for (int vh = 0; vh < 4; vh++)
#pragma unroll
                for (int vw = 0; vw < 4; vw++)
                    Keff[uh + vh][uw + vw] += wv * kq[vh] * kq[vw];
        }

    int half = oc >> 7, m = oc & 127;
    int kin = c & 63;
#pragma unroll
    for (int p = 0; p < 4; p++) {
        int ph = p >> 1, pw = p & 1;
#pragma unroll
        for (int th = 0; th < 3; th++)
#pragma unroll
            for (int tw = 0; tw < 3; tw++) {
                float v = Keff[2 * th + 1 - ph][2 * tw + 1 - pw];
                __nv_bfloat16 vh = __float2bfloat16(v);
                __nv_bfloat16 vl = __float2bfloat16(v - __bfloat162float(vh));
                int kc = (th * 3 + tw) * 4 + (c >> 6);
                uint32_t off = (uint32_t)((p * 2 + half) * 36 + kc) * 16384u
                             + (uint32_t)m * 128u + (uint32_t)kin * 2u;
                *(__nv_bfloat16*)(g_Wh + off) = vh;
                *(__nv_bfloat16*)(g_Wl + off) = vl;
            }
    }
}

// ---------------------------------------------------------------------------
// prep 2: x fp32 -> packed bf16 h/l c-pair words
// ---------------------------------------------------------------------------
__global__ void prep_x_kernel(const float* __restrict__ x) {
    int idx = blockIdx.x * blockDim.x + threadIdx.x;   // 0 .. 8*128*4096-1
    int hw = idx & 4095;
    int c2 = (idx >> 12) & 127;
    int n  = idx >> 19;
    const float* px = x + ((size_t)n * CIN + 2 * c2) * 4096 + hw;
    float v0 = px[0], v1 = px[4096];
    __nv_bfloat16 h0 = __float2bfloat16(v0);
    __nv_bfloat16 h1 = __float2bfloat16(v1);
    __nv_bfloat16 l0 = __float2bfloat16(v0 - __bfloat162float(h0));
    __nv_bfloat16 l1 = __float2bfloat16(v1 - __bfloat162float(h1));
    g_Xh[idx] = (uint32_t)__bfloat16_as_ushort(h0) | ((uint32_t)__bfloat16_as_ushort(h1) << 16);
    g_Xl[idx] = (uint32_t)__bfloat16_as_ushort(l0) | ((uint32_t)__bfloat16_as_ushort(l1) << 16);
}

// ---------------------------------------------------------------------------
// main: grid (256, 2 oc-halves, 4 parities), 512 threads, 128KB dyn smem
// stage s (64KB): Ah @+0, Al @+16K, Bh @+32K, Bl @+48K (all SW128-swizzled)
// warp w: tile m [wm*32, +32) x n [wn*32, +32), wm=w&3, wn=w>>2
// ---------------------------------------------------------------------------
__global__ __launch_bounds__(512, 1) void conv_mma_kernel(
    const float* __restrict__ bias, float* __restrict__ out)
{
    extern __shared__ char smem[];
    const uint32_t sb = smem_u32(smem);
    const int tid = threadIdx.x;
    const int warp = tid >> 5, lane = tid & 31;

    const int bx = blockIdx.x;
    const int n = bx >> 5, t = bx & 31;
    const int ih0 = (t >> 2) * 8, iw0 = (t & 3) * 16;
    const int ochalf = blockIdx.y;
    const int p = blockIdx.z;
    const int ph = p >> 1, pw = p & 1;

    const int wm = warp & 3, wn = warp >> 2;

    float acc[2][4][4];
#pragma unroll
    for (int mf = 0; mf < 2; mf++)
#pragma unroll
        for (int nf = 0; nf < 4; nf++)
#pragma unroll
            for (int i = 0; i < 4; i++) acc[mf][nf][i] = 0.0f;

    // --- per-thread B prefetch geometry
    const int cw = tid & 15, rest = tid >> 4;
    const int rB = rest & 7, cg = rest >> 3;     // cg 0..3: 8 c-pairs each

    // --- per-thread ldmatrix geometry
    const int rowA0 = wm * 32 + (lane & 7) + ((lane >> 3) & 1) * 8;
    const int kbA = ((lane >> 4) & 1) * 16;
    const int rowB0 = wn * 32 + (lane & 7);
    const int kbB = ((lane >> 3) & 1) * 16;

    const unsigned char* wbh = g_Wh + (size_t)((p * 2 + ochalf) * 36) * 16384;
    const unsigned char* wbl = g_Wl + (size_t)((p * 2 + ochalf) * 36) * 16384;

#define PREFETCH(kc, s) do {                                                        \
    const unsigned char* srcH = wbh + (size_t)(kc) * 16384;                         \
    const unsigned char* srcL = wbl + (size_t)(kc) * 16384;                         \
    uint32_t stg = sb + (uint32_t)(s) * 65536u;                                     \
    _Pragma("unroll")                                                               \
    for (int i = 0; i < 2; i++) {                                                   \
        uint32_t v = (uint32_t)(i * 512 + tid) * 16u;                               \
        CP16(stg + swz(v), srcH + v);                                               \
        CP16(stg + 16384u + swz(v), srcL + v);                                      \
    }                                                                               \
    {                                                                               \
        int tap = (kc) >> 2;                                                        \
        int th = tap / 3, tw = tap - th * 3;                                        \
        int cpb = ((kc) & 3) * 32;                                                  \
        int gh = ih0 + rB - 1 + th, gw = iw0 + cw - 1 + tw;                         \
        int inb = ((unsigned)gh < 64u && (unsigned)gw < 64u) ? 4 : 0;               \
        uint32_t gidx = (uint32_t)((n * 128 + cpb) * 4096)                          \
                        + (inb ? (uint32_t)(gh * 64 + gw) : 0u);                    \
        uint32_t brow = (uint32_t)(rB * 16 + cw) * 128u;                            \
        _Pragma("unroll")                                                           \
        for (int i = 0; i < 8; i++) {                                               \
            int c2 = cg * 8 + i;                                                    \
            uint32_t doff = swz(brow + (uint32_t)c2 * 4u);                          \
            CP4Z(stg + 32768u + doff, g_Xh + gidx + c2 * 4096, inb);                \
            CP4Z(stg + 49152u + doff, g_Xl + gidx + c2 * 4096, inb);                \
        }                                                                           \
    }                                                                               \
} while (0)

    PREFETCH(0, 0);
    CP_COMMIT();

    for (int kc = 0; kc < 36; kc++) {
        const int s = kc & 1;
        if (kc + 1 < 36) {
            PREFETCH(kc + 1, s ^ 1);
            CP_COMMIT();
            CP_WAIT1();
        } else {
            CP_WAIT0();
        }
        __syncthreads();

        const uint32_t A0 = sb + (uint32_t)s * 65536u;
        const uint32_t A1 = A0 + 16384u;
        const uint32_t B0 = A0 + 32768u;
        const uint32_t B1 = A0 + 49152u;

#pragma unroll
        for (int ks = 0; ks < 4; ks++) {
            uint32_t ah[2][4], al[2][4], bh[4][2], bl[4][2];
#pragma unroll
            for (int mf = 0; mf < 2; mf++) {
                uint32_t ao = swz((uint32_t)(rowA0 + mf * 16) * 128u + (uint32_t)(ks * 32 + kbA));
                LDSM4(ah[mf], A0 + ao);
                LDSM4(al[mf], A1 + ao);
            }
#pragma unroll
            for (int nf = 0; nf < 4; nf++) {
                uint32_t bo = swz((uint32_t)(rowB0 + nf * 8) * 128u + (uint32_t)(ks * 32 + kbB));
                LDSM2(bh[nf], B0 + bo);
                LDSM2(bl[nf], B1 + bo);
            }
#pragma unroll
            for (int mf = 0; mf < 2; mf++)
#pragma unroll
                for (int nf = 0; nf < 4; nf++) {
                    MMA(acc[mf][nf], ah[mf], bh[nf]);
                    MMA(acc[mf][nf], al[mf], bh[nf]);
                    MMA(acc[mf][nf], ah[mf], bl[nf]);
                }
        }
        __syncthreads();
    }

    // ---- epilogue: accums -> smem [oc][pos] (pitch 132), then coalesced out
    float* ep = (float*)smem;
    {
        int g = lane >> 2, tq = lane & 3;
#pragma unroll
        for (int mf = 0; mf < 2; mf++)
#pragma unroll
            for (int nf = 0; nf < 4; nf++) {
                int row = wm * 32 + mf * 16 + g;
                int col = wn * 32 + nf * 8 + tq * 2;
                ep[row * 132 + col]           = acc[mf][nf][0];
                ep[row * 132 + col + 1]       = acc[mf][nf][1];
                ep[(row + 8) * 132 + col]     = acc[mf][nf][2];
                ep[(row + 8) * 132 + col + 1] = acc[mf][nf][3];
            }
    }
    __syncthreads();

    for (int e = tid; e < 16384; e += 512) {
        int ocl = e >> 7, posi = e & 127;
        int r = posi >> 4, c = posi & 15;
        int oc = ochalf * 128 + ocl;
        float v = ep[ocl * 132 + posi] + bias[oc];
        out[(((size_t)n * OCH + oc) * 128 + 2 * (ih0 + r) + ph) * 128
            + 2 * (iw0 + c) + pw] = v;
    }
}

extern "C" void kernel_launch(void* const* d_in, const int* in_sizes, int n_in,
                              void* d_out, int out_size) {
    const float* hidden = (const float*)d_in[0];   // (8,256,64,64)
    const float* weight = (const float*)d_in[1];   // (256,256,3,3)
    const float* bias   = (const float*)d_in[2];   // (256,)
    float* out = (float*)d_out;                    // (8,256,128,128)

    cudaFuncSetAttribute(conv_mma_kernel,
                         cudaFuncAttributeMaxDynamicSharedMemorySize, 131072);

    prep_weff_kernel<<<256, 256>>>(weight);
    prep_x_kernel<<<8192, 512>>>(hidden);
    conv_mma_kernel<<<dim3(256, 2, 4), 512, 131072>>>(bias, out);
}